// round 15
// baseline (speedup 1.0000x reference)
#include <cuda_runtime.h>
#include <cuda_bf16.h>

// 3x3 high-pass stencil: y = |0.125*(hs_top+hs_mid+hs_bot) - 1.125*center| + 1e-5
// x: (8,32,512,512) fp32, zero-padded SAME. Register-rolling, smem-free.
// Warp strip: 128 cols x 32 rows, prefetch d=2, __ldcg loads, __stcs stores,
// fully unrolled, single rolling pointer (edge derived as rp+d), 6 CTAs/SM.

#define W 512
#define H 512
#define ROWS 32
#define WARPS 8
#define TW 128

struct Row {
    float4 v;   // lane's 4 columns
    float  e;   // strip-edge neighbor (lane 0: left, lane 31: right)
};

// rp: this lane's vec4 address in the row; ed: edge offset from rp;
// has_edge: lane 0/31 with in-image halo col; rr: row index for the v-guard.
__device__ __forceinline__ Row load_row(const float* rp, int ed, bool has_edge, int rr) {
    Row o;
    o.e = 0.f;
    if ((unsigned)rr < H) {
        o.v = __ldcg(reinterpret_cast<const float4*>(rp));
        if (has_edge) o.e = __ldcg(rp + ed);
    } else {
        o.v = make_float4(0.f, 0.f, 0.f, 0.f);
    }
    return o;
}

__device__ __forceinline__ float4 hsum(const Row& rw, bool lo, bool hi) {
    float l = __shfl_up_sync(0xffffffffu, rw.v.w, 1);
    if (lo) l = rw.e;
    float r = __shfl_down_sync(0xffffffffu, rw.v.x, 1);
    if (hi) r = rw.e;
    float4 h;
    h.x = l      + rw.v.x + rw.v.y;
    h.y = rw.v.x + rw.v.y + rw.v.z;
    h.z = rw.v.y + rw.v.z + rw.v.w;
    h.w = rw.v.z + rw.v.w + r;
    return h;
}

__global__ __launch_bounds__(256, 6)
void highpass_kernel(const float* __restrict__ x, float* __restrict__ y) {
    const int warp = threadIdx.x >> 5;
    const int lane = threadIdx.x & 31;

    const int c0    = blockIdx.x * TW;
    const int rbase = (blockIdx.y * WARPS + warp) * ROWS;
    const int col   = c0 + lane * 4;

    const float* __restrict__ xp = x + ((size_t)blockIdx.z << 18);
    float* __restrict__ yp       = y + ((size_t)blockIdx.z << 18);

    // lane-constant edge config (predicates + one small immediate)
    const bool lo = (lane == 0);
    const bool hi = (lane == 31);
    const int  ed = lo ? -1 : 4;                       // edge addr = rp + ed
    const bool has_edge = (lo && c0 > 0) || (hi && c0 + TW < W);

    // rolling state: one input pointer, one output pointer, one row index
    const float* rp = xp + (rbase - 1) * W + col;
    float* op = yp + rbase * W + col;
    int rr = rbase - 1;

    // prime the pipeline: rows rbase-1 .. rbase+2
    Row rm  = load_row(rp, ed, has_edge, rr);  rp += W; rr++;
    Row rc  = load_row(rp, ed, has_edge, rr);  rp += W; rr++;
    Row rn  = load_row(rp, ed, has_edge, rr);  rp += W; rr++;
    Row rn2 = load_row(rp, ed, has_edge, rr);  rp += W; rr++;

    float4 hsA = hsum(rm, lo, hi);
    float4 hsB = hsum(rc, lo, hi);
    float4 vc  = rc.v;

    #pragma unroll
    for (int i = 0; i < ROWS; i++) {
        Row rn3 = load_row(rp, ed, has_edge, rr);  // prefetch d=2
        rp += W; rr++;

        float4 hsC = hsum(rn, lo, hi);

        float4 o;
        o.x = fabsf(0.125f * (hsA.x + hsB.x + hsC.x) - 1.125f * vc.x) + 1e-5f;
        o.y = fabsf(0.125f * (hsA.y + hsB.y + hsC.y) - 1.125f * vc.y) + 1e-5f;
        o.z = fabsf(0.125f * (hsA.z + hsB.z + hsC.z) - 1.125f * vc.z) + 1e-5f;
        o.w = fabsf(0.125f * (hsA.w + hsB.w + hsC.w) - 1.125f * vc.w) + 1e-5f;

        __stcs(reinterpret_cast<float4*>(op), o);   // streaming store
        op += W;

        hsA = hsB; hsB = hsC; vc = rn.v; rn = rn2; rn2 = rn3;
    }
}

extern "C" void kernel_launch(void* const* d_in, const int* in_sizes, int n_in,
                              void* d_out, int out_size) {
    const float* x = (const float*)d_in[0];
    float* y = (float*)d_out;

    const int planes = out_size / (W * H);           // 256
    dim3 block(256, 1, 1);                           // 8 warps
    dim3 grid(W / TW, H / (ROWS * WARPS), planes);   // (4, 2, 256) = 2048 CTAs
    highpass_kernel<<<grid, block>>>(x, y);
}

// round 16
// speedup vs baseline: 1.0371x; 1.0371x over previous
#include <cuda_runtime.h>
#include <cuda_bf16.h>

// 3x3 high-pass stencil: y = |0.125*(hs_top+hs_mid+hs_bot) - 1.125*center| + 1e-5
// x: (8,32,512,512) fp32, zero-padded SAME. Register-rolling, smem-free.
// Warp strip: 128 cols x 32 rows, prefetch d=2, __ldcg loads, __stcs stores,
// fully unrolled, rolling pointers. 128-thr CTAs (4 warps) x min_blocks=10:
// same 40 warps/SM and same 51-reg cap as the 256x5 shape, but CTA duration
// halves -> end-of-kernel drain halves.

#define W 512
#define H 512
#define ROWS 32
#define WARPS 4
#define TW 128

struct Row {
    float4 v;   // lane's 4 columns
    float  e;   // strip-edge neighbor: left on lane 0, right on lane 31
};

// rp: pointer to this lane's vec4 in row rr; ep: edge pointer (or null); rr for guard
__device__ __forceinline__ Row load_row(const float* rp, const float* ep, int rr) {
    Row o;
    o.e = 0.f;
    if ((unsigned)rr < H) {
        o.v = __ldcg(reinterpret_cast<const float4*>(rp));
        if (ep) o.e = __ldcg(ep);
    } else {
        o.v = make_float4(0.f, 0.f, 0.f, 0.f);
    }
    return o;
}

__device__ __forceinline__ float4 hsum(const Row& rw, int lane) {
    float l = __shfl_up_sync(0xffffffffu, rw.v.w, 1);
    if (lane == 0) l = rw.e;
    float r = __shfl_down_sync(0xffffffffu, rw.v.x, 1);
    if (lane == 31) r = rw.e;
    float4 h;
    h.x = l      + rw.v.x + rw.v.y;
    h.y = rw.v.x + rw.v.y + rw.v.z;
    h.z = rw.v.y + rw.v.z + rw.v.w;
    h.w = rw.v.z + rw.v.w + r;
    return h;
}

__global__ __launch_bounds__(128, 10)
void highpass_kernel(const float* __restrict__ x, float* __restrict__ y) {
    const int warp = threadIdx.x >> 5;
    const int lane = threadIdx.x & 31;

    const int c0    = blockIdx.x * TW;
    const int rbase = (blockIdx.y * WARPS + warp) * ROWS;
    const int col   = c0 + lane * 4;

    const float* __restrict__ xp = x + ((size_t)blockIdx.z << 18);
    float* __restrict__ yp       = y + ((size_t)blockIdx.z << 18);

    // rolling pointers (start at row rbase-1)
    const float* rp = xp + (rbase - 1) * W + col;

    // hoisted edge pointer: lane 0 -> left halo col, lane 31 -> right halo col
    const float* ep = nullptr;
    if (lane == 0) {
        if (c0 > 0) ep = xp + (rbase - 1) * W + (c0 - 1);
    } else if (lane == 31) {
        if (c0 + TW < W) ep = xp + (rbase - 1) * W + (c0 + TW);
    }
    const int epinc = ep ? W : 0;

    // prime the pipeline: rows rbase-1 .. rbase+2
    Row rm  = load_row(rp, ep, rbase - 1);  rp += W; ep += epinc;
    Row rc  = load_row(rp, ep, rbase);      rp += W; ep += epinc;
    Row rn  = load_row(rp, ep, rbase + 1);  rp += W; ep += epinc;
    Row rn2 = load_row(rp, ep, rbase + 2);  rp += W; ep += epinc;

    float4 hsA = hsum(rm, lane);
    float4 hsB = hsum(rc, lane);
    float4 vc  = rc.v;

    float* op = yp + rbase * W + col;

    #pragma unroll
    for (int i = 0; i < ROWS; i++) {
        Row rn3 = load_row(rp, ep, rbase + i + 3);  // prefetch d=2
        rp += W; ep += epinc;

        float4 hsC = hsum(rn, lane);

        float4 o;
        o.x = fabsf(0.125f * (hsA.x + hsB.x + hsC.x) - 1.125f * vc.x) + 1e-5f;
        o.y = fabsf(0.125f * (hsA.y + hsB.y + hsC.y) - 1.125f * vc.y) + 1e-5f;
        o.z = fabsf(0.125f * (hsA.z + hsB.z + hsC.z) - 1.125f * vc.z) + 1e-5f;
        o.w = fabsf(0.125f * (hsA.w + hsB.w + hsC.w) - 1.125f * vc.w) + 1e-5f;

        __stcs(reinterpret_cast<float4*>(op), o);   // streaming store
        op += W;

        hsA = hsB; hsB = hsC; vc = rn.v; rn = rn2; rn2 = rn3;
    }
}

extern "C" void kernel_launch(void* const* d_in, const int* in_sizes, int n_in,
                              void* d_out, int out_size) {
    const float* x = (const float*)d_in[0];
    float* y = (float*)d_out;

    const int planes = out_size / (W * H);           // 256
    dim3 block(128, 1, 1);                           // 4 warps
    dim3 grid(W / TW, H / (ROWS * WARPS), planes);   // (4, 4, 256) = 4096 CTAs
    highpass_kernel<<<grid, block>>>(x, y);
}